// round 9
// baseline (speedup 1.0000x reference)
#include <cuda_runtime.h>
#include <cuda_fp16.h>

#define T_TOK 2048
#define H_DIM 1024
#define F_DIM 3584
#define N_EXP 8
#define CAP   2048
#define TOTROW 4096

// ---------------- device scratch ----------------
__device__ int   g_count[N_EXP];
__device__ int   g_off[N_EXP];
__device__ int   g_tok[N_EXP * CAP];
__device__ int   g_te[T_TOK * 2];
__device__ int   g_tslot[T_TOK * 2];
__device__ float g_tw[T_TOK * 2];

__device__ __half g_xh[(size_t)T_TOK * H_DIM];
__device__ __half g_w1h[(size_t)N_EXP * F_DIM * H_DIM];
__device__ __half g_w3h[(size_t)N_EXP * F_DIM * H_DIM];
__device__ __half g_w2h[(size_t)N_EXP * H_DIM * F_DIM];
__device__ __half g_act[(size_t)TOTROW * F_DIM];
__device__ float  g_outp[(size_t)TOTROW * H_DIM];

// ---------------- helpers ----------------
__device__ __forceinline__ unsigned s2u(const void* p) {
    unsigned a;
    asm("{ .reg .u64 t; cvta.to.shared.u64 t, %1; cvt.u32.u64 %0, t; }" : "=r"(a) : "l"(p));
    return a;
}
// 128B-row swizzle: 16B chunk index XOR (row & 7)
__device__ __forceinline__ unsigned swz(int row, int chunk) {
    return (unsigned)(row * 128 + ((chunk ^ (row & 7)) << 4));
}

#define LDSM_X4(r0, r1, r2, r3, a)                                           \
    asm volatile("ldmatrix.sync.aligned.m8n8.x4.shared.b16 {%0,%1,%2,%3}, [%4];" \
                 : "=r"(r0), "=r"(r1), "=r"(r2), "=r"(r3) : "r"(a))

#define MMA16816(d, a, b0, b1)                                               \
    asm volatile("mma.sync.aligned.m16n8k16.row.col.f32.f16.f16.f32 "        \
                 "{%0,%1,%2,%3},{%4,%5,%6,%7},{%8,%9},{%0,%1,%2,%3};"        \
                 : "+f"((d)[0]), "+f"((d)[1]), "+f"((d)[2]), "+f"((d)[3])    \
                 : "r"((a)[0]), "r"((a)[1]), "r"((a)[2]), "r"((a)[3]),       \
                   "r"(b0), "r"(b1))

// ---------------- kernel: fp32 -> fp16 convert (dst chosen device-side) ----------------
__global__ void k_cvt(const float* __restrict__ s, int which, size_t n4) {
    __half* h;
    switch (which) {
        case 0: h = g_xh;  break;
        case 1: h = g_w1h; break;
        case 2: h = g_w3h; break;
        default: h = g_w2h; break;
    }
    size_t i = (size_t)blockIdx.x * blockDim.x + threadIdx.x;
    size_t stride = (size_t)gridDim.x * blockDim.x;
    for (; i < n4; i += stride) {
        float4 v = ((const float4*)s)[i];
        ushort4 hv;
        hv.x = __half_as_ushort(__float2half_rn(v.x));
        hv.y = __half_as_ushort(__float2half_rn(v.y));
        hv.z = __half_as_ushort(__float2half_rn(v.z));
        hv.w = __half_as_ushort(__float2half_rn(v.w));
        ((ushort4*)h)[i] = hv;
    }
}

// ---------------- kernel: gating ----------------
__global__ void k_gate(const float* __restrict__ x, const float* __restrict__ gw) {
    __shared__ float sgw[H_DIM * N_EXP];
    for (int i = threadIdx.x; i < H_DIM * N_EXP; i += 256) sgw[i] = gw[i];
    __syncthreads();

    int warp = threadIdx.x >> 5, lane = threadIdx.x & 31;
    int t = blockIdx.x * 8 + warp;
    if (t >= T_TOK) return;

    float acc[N_EXP];
#pragma unroll
    for (int e = 0; e < N_EXP; e++) acc[e] = 0.f;
    const float* xr = x + (size_t)t * H_DIM;
    for (int h = lane; h < H_DIM; h += 32) {
        float xv = xr[h];
#pragma unroll
        for (int e = 0; e < N_EXP; e++) acc[e] = fmaf(xv, sgw[h * N_EXP + e], acc[e]);
    }
#pragma unroll
    for (int e = 0; e < N_EXP; e++) {
#pragma unroll
        for (int o = 16; o > 0; o >>= 1) acc[e] += __shfl_xor_sync(0xffffffffu, acc[e], o);
    }
    if (lane == 0) {
        int e0 = 0; float m0 = acc[0];
#pragma unroll
        for (int e = 1; e < N_EXP; e++) if (acc[e] > m0) { m0 = acc[e]; e0 = e; }
        int e1 = -1; float m1 = -3.4e38f;
#pragma unroll
        for (int e = 0; e < N_EXP; e++) if (e != e0 && acc[e] > m1) { m1 = acc[e]; e1 = e; }
        float w0 = 1.f / (1.f + __expf(m1 - m0));
        g_te[2 * t] = e0;  g_te[2 * t + 1] = e1;
        g_tw[2 * t] = w0;  g_tw[2 * t + 1] = 1.f - w0;
    }
}

// ---------------- kernel: per-expert token lists ----------------
__global__ void k_build() {
    int e = threadIdx.x >> 5, lane = threadIdx.x & 31;
    int cnt = 0;
    for (int base = 0; base < T_TOK; base += 32) {
        int t = base + lane;
        int a = g_te[2 * t], b = g_te[2 * t + 1];
        bool f1 = (b == e);
        bool f  = (a == e) || f1;
        unsigned mask = __ballot_sync(0xffffffffu, f);
        int pos = cnt + __popc(mask & ((1u << lane) - 1u));
        if (f) {
            g_tok[e * CAP + pos] = t;
            g_tslot[2 * t + (f1 ? 1 : 0)] = pos;
        }
        cnt += __popc(mask);
    }
    if (lane == 0) g_count[e] = cnt;
    __syncthreads();
    if (threadIdx.x == 0) {
        int o = 0;
        for (int i = 0; i < N_EXP; i++) { g_off[i] = o; o += g_count[i]; }
    }
}

// ---------------- kernel: stage-1 (h = X w1^T, g = X w3^T) + SwiGLU ----------------
// R8 structure + register-prefetch of the next K-chunk (smem layout/indexing unchanged).
__global__ __launch_bounds__(256, 2) void k_ffn1() {
    __shared__ __align__(1024) char sm[32768];

    int e = blockIdx.z;
    int count = g_count[e];
    int row0 = blockIdx.y * 128;
    if (row0 >= count) return;
    int fBase = blockIdx.x * 64;

    int tid = threadIdx.x, lane = tid & 31, wid = tid >> 5;
    int wm = wid >> 1, wn = wid & 1;
    unsigned sb = s2u(sm);
    const unsigned OA = 0, O1H = 16384, O3H = 24576;

    int jc = tid & 7;                 // 16B chunk within 128B row
    int rbase = tid >> 3;             // 0..31
    const __half* aptr[4];
#pragma unroll
    for (int it = 0; it < 4; it++) {
        int row = rbase + it * 32;
        int r = row0 + row;
        int tok = (r < count) ? g_tok[e * CAP + r] : -1;
        aptr[it] = (tok >= 0) ? (g_xh + (size_t)tok * H_DIM + jc * 8) : 0;
    }
    const __half* w1p0 = g_w1h + ((size_t)e * F_DIM + fBase + rbase) * H_DIM + jc * 8;
    const __half* w1p1 = w1p0 + (size_t)32 * H_DIM;
    const __half* w3p0 = g_w3h + ((size_t)e * F_DIM + fBase + rbase) * H_DIM + jc * 8;
    const __half* w3p1 = w3p0 + (size_t)32 * H_DIM;

    float acc1[2][4][4], acc3[2][4][4];
#pragma unroll
    for (int i = 0; i < 2; i++)
#pragma unroll
        for (int j = 0; j < 4; j++)
#pragma unroll
            for (int q = 0; q < 4; q++) { acc1[i][j][q] = 0.f; acc3[i][j][q] = 0.f; }

    // prefetch K-chunk 0
    uint4 pa[4], p1[2], p3[2];
#pragma unroll
    for (int it = 0; it < 4; it++)
        pa[it] = aptr[it] ? *(const uint4*)(aptr[it]) : make_uint4(0, 0, 0, 0);
    p1[0] = *(const uint4*)(w1p0); p1[1] = *(const uint4*)(w1p1);
    p3[0] = *(const uint4*)(w3p0); p3[1] = *(const uint4*)(w3p1);

    for (int kt = 0; kt < H_DIM; kt += 64) {
        // commit prefetched regs to smem
#pragma unroll
        for (int it = 0; it < 4; it++)
            *(uint4*)(sm + OA + swz(rbase + it * 32, jc)) = pa[it];
        *(uint4*)(sm + O1H + swz(rbase,      jc)) = p1[0];
        *(uint4*)(sm + O1H + swz(rbase + 32, jc)) = p1[1];
        *(uint4*)(sm + O3H + swz(rbase,      jc)) = p3[0];
        *(uint4*)(sm + O3H + swz(rbase + 32, jc)) = p3[1];
        __syncthreads();

        // prefetch next K-chunk (overlaps with MMA below)
        int ktn = kt + 64;
        if (ktn < H_DIM) {
#pragma unroll
            for (int it = 0; it < 4; it++)
                pa[it] = aptr[it] ? *(const uint4*)(aptr[it] + ktn) : make_uint4(0, 0, 0, 0);
            p1[0] = *(const uint4*)(w1p0 + ktn); p1[1] = *(const uint4*)(w1p1 + ktn);
            p3[0] = *(const uint4*)(w3p0 + ktn); p3[1] = *(const uint4*)(w3p1 + ktn);
        }

#pragma unroll
        for (int ks = 0; ks < 4; ks++) {
            unsigned af[2][4];
#pragma unroll
            for (int mt = 0; mt < 2; mt++) {
                int row = wm * 32 + mt * 16 + ((lane >> 3) & 1) * 8 + (lane & 7);
                int ch  = 2 * ks + (lane >> 4);
                LDSM_X4(af[mt][0], af[mt][1], af[mt][2], af[mt][3], sb + OA + swz(row, ch));
            }
            int wrow = wn * 32 + ((lane >> 4) & 1) * 8 + (lane & 7);
            int wch  = 2 * ks + ((lane >> 3) & 1);
#pragma unroll
            for (int ntp = 0; ntp < 4; ntp += 2) {
                unsigned d = swz(wrow + ntp * 8, wch);
                unsigned b1[4], b3[4];
                LDSM_X4(b1[0], b1[1], b1[2], b1[3], sb + O1H + d);
                LDSM_X4(b3[0], b3[1], b3[2], b3[3], sb + O3H + d);
#pragma unroll
                for (int mt = 0; mt < 2; mt++) {
                    MMA16816(acc1[mt][ntp],     af[mt], b1[0], b1[1]);
                    MMA16816(acc1[mt][ntp + 1], af[mt], b1[2], b1[3]);
                    MMA16816(acc3[mt][ntp],     af[mt], b3[0], b3[1]);
                    MMA16816(acc3[mt][ntp + 1], af[mt], b3[2], b3[3]);
                }
            }
        }
        __syncthreads();
    }

    // epilogue: SwiGLU -> fp16 activations
    int rb = row0 + wm * 32, cb = fBase + wn * 32;
    size_t obase = (size_t)g_off[e] * F_DIM;
#pragma unroll
    for (int mt = 0; mt < 2; mt++) {
#pragma unroll
        for (int nt = 0; nt < 4; nt++) {
            int r = rb + mt * 16 + (lane >> 2);
            int c = cb + nt * 8 + (lane & 3) * 2;
#pragma unroll
            for (int half = 0; half < 2; half++) {
                int rr = r + half * 8;
                if (rr < count) {
                    float h0 = acc1[mt][nt][half * 2],     g0 = acc3[mt][nt][half * 2];
                    float h1 = acc1[mt][nt][half * 2 + 1], g1 = acc3[mt][nt][half * 2 + 1];
                    float a0 = (h0 / (1.f + __expf(-h0))) * g0;
                    float a1 = (h1 / (1.f + __expf(-h1))) * g1;
                    __half2 v = __floats2half2_rn(a0, a1);
                    *(__half2*)(g_act + obase + (size_t)rr * F_DIM + c) = v;
                }
            }
        }
    }
}

// ---------------- kernel: stage-2 (out = act @ w2^T) ----------------
// R8 structure + register-prefetch of the next K-chunk.
__global__ __launch_bounds__(256, 2) void k_ffn2() {
    __shared__ __align__(1024) char sm[32768];

    int e = blockIdx.z;
    int count = g_count[e];
    int row0 = blockIdx.y * 128;
    if (row0 >= count) return;
    int hBase = blockIdx.x * 128;

    int tid = threadIdx.x, lane = tid & 31, wid = tid >> 5;
    int wm = wid >> 1, wn = wid & 1;
    unsigned sb = s2u(sm);
    const unsigned OA = 0, OBH = 16384;

    int rmax = count - row0; if (rmax > 128) rmax = 128;
    size_t rowBase = (size_t)(g_off[e] + row0);
    int jc = tid & 7, rbase = tid >> 3;

    const __half* apt[4];
    const __half* bpt[4];
#pragma unroll
    for (int it = 0; it < 4; it++) {
        int row = rbase + it * 32;
        apt[it] = (row < rmax) ? (g_act + (rowBase + row) * F_DIM + jc * 8) : 0;
        bpt[it] = g_w2h + ((size_t)e * H_DIM + hBase + row) * F_DIM + jc * 8;
    }

    float acc[2][8][4];
#pragma unroll
    for (int i = 0; i < 2; i++)
#pragma unroll
        for (int j = 0; j < 8; j++)
#pragma unroll
            for (int q = 0; q < 4; q++) acc[i][j][q] = 0.f;

    // prefetch K-chunk 0
    uint4 pa[4], pb[4];
#pragma unroll
    for (int it = 0; it < 4; it++) {
        pa[it] = apt[it] ? *(const uint4*)(apt[it]) : make_uint4(0, 0, 0, 0);
        pb[it] = *(const uint4*)(bpt[it]);
    }

    for (int kt = 0; kt < F_DIM; kt += 64) {
#pragma unroll
        for (int it = 0; it < 4; it++) {
            int row = rbase + it * 32;
            *(uint4*)(sm + OA  + swz(row, jc)) = pa[it];
            *(uint4*)(sm + OBH + swz(row, jc)) = pb[it];
        }
        __syncthreads();

        int ktn = kt + 64;
        if (ktn < F_DIM) {
#pragma unroll
            for (int it = 0; it < 4; it++) {
                pa[it] = apt[it] ? *(const uint4*)(apt[it] + ktn) : make_uint4(0, 0, 0, 0);
                pb[it] = *(const uint4*)(bpt[it] + ktn);
            }
        }

#pragma unroll
        for (int ks = 0; ks < 4; ks++) {
            unsigned af[2][4];
#pragma unroll
            for (int mt = 0; mt < 2; mt++) {
                int row = wm * 32 + mt * 16 + ((lane >> 3) & 1) * 8 + (lane & 7);
                int ch  = 2 * ks + (lane >> 4);
                LDSM_X4(af[mt][0], af[mt][1], af[mt][2], af[mt][3], sb + OA + swz(row, ch));
            }
            int wrow = wn * 64 + ((lane >> 4) & 1) * 8 + (lane & 7);
            int wch  = 2 * ks + ((lane >> 3) & 1);
#pragma unroll
            for (int ntp = 0; ntp < 8; ntp += 2) {
                unsigned d = swz(wrow + ntp * 8, wch);
                unsigned bh[4];
                LDSM_X4(bh[0], bh[1], bh[2], bh[3], sb + OBH + d);
#pragma unroll
                for (int mt = 0; mt < 2; mt++) {
                    MMA16816(acc[mt][ntp],     af[mt], bh[0], bh[1]);
                    MMA16816(acc[mt][ntp + 1], af[mt], bh[2], bh[3]);
                }
            }
        }
        __syncthreads();
    }

    int rb = wm * 32, cb = hBase + wn * 64;
#pragma unroll
    for (int mt = 0; mt < 2; mt++) {
#pragma unroll
        for (int nt = 0; nt < 8; nt++) {
            int r = rb + mt * 16 + (lane >> 2);
            int c = cb + nt * 8 + (lane & 3) * 2;
#pragma unroll
            for (int half = 0; half < 2; half++) {
                int rr = r + half * 8;
                if (rr < rmax) {
                    float2 v = make_float2(acc[mt][nt][half * 2], acc[mt][nt][half * 2 + 1]);
                    *(float2*)(g_outp + (rowBase + rr) * H_DIM + c) = v;
                }
            }
        }
    }
}

// ---------------- kernel: weighted combine ----------------
__global__ void k_comb(float* __restrict__ out) {
    int t = blockIdx.x;
    int e0 = g_te[2 * t], e1 = g_te[2 * t + 1];
    int s0 = g_off[e0] + g_tslot[2 * t], s1 = g_off[e1] + g_tslot[2 * t + 1];
    float w0 = g_tw[2 * t], w1 = g_tw[2 * t + 1];
    const float4* p0 = (const float4*)(g_outp + (size_t)s0 * H_DIM);
    const float4* p1 = (const float4*)(g_outp + (size_t)s1 * H_DIM);
    float4* o = (float4*)(out + (size_t)t * H_DIM);
    for (int h = threadIdx.x; h < H_DIM / 4; h += 256) {
        float4 a = p0[h], b = p1[h];
        o[h] = make_float4(w0 * a.x + w1 * b.x, w0 * a.y + w1 * b.y,
                           w0 * a.z + w1 * b.z, w0 * a.w + w1 * b.w);
    }
}

// ---------------- launch (kernel launches ONLY, no dynamic smem) ----------------
extern "C" void kernel_launch(void* const* d_in, const int* in_sizes, int n_in,
                              void* d_out, int out_size) {
    const float* x  = (const float*)d_in[0];
    const float* gw = (const float*)d_in[1];
    const float* w1 = (const float*)d_in[2];
    const float* w3 = (const float*)d_in[3];
    const float* w2 = (const float*)d_in[4];
    float* out = (float*)d_out;

    k_gate<<<T_TOK / 8, 256>>>(x, gw);
    k_build<<<1, 256>>>();

    size_t nx = (size_t)T_TOK * H_DIM / 4;
    size_t nw = (size_t)N_EXP * F_DIM * H_DIM / 4;
    k_cvt<<<512, 256>>>(x, 0, nx);
    k_cvt<<<2048, 256>>>(w1, 1, nw);
    k_cvt<<<2048, 256>>>(w3, 2, nw);
    k_cvt<<<2048, 256>>>(w2, 3, nw);

    k_ffn1<<<dim3(F_DIM / 64, CAP / 128, N_EXP), 256>>>();
    k_ffn2<<<dim3(H_DIM / 128, CAP / 128, N_EXP), 256>>>();
    k_comb<<<T_TOK, 256>>>(out);
}

// round 10
// speedup vs baseline: 1.1131x; 1.1131x over previous
#include <cuda_runtime.h>
#include <cuda_fp16.h>

#define T_TOK 2048
#define H_DIM 1024
#define F_DIM 3584
#define N_EXP 8
#define CAP   2048
#define TOTROW 4096

// ---------------- device scratch ----------------
__device__ int   g_count[N_EXP];
__device__ int   g_off[N_EXP];
__device__ int   g_tok[N_EXP * CAP];
__device__ int   g_te[T_TOK * 2];
__device__ int   g_tslot[T_TOK * 2];
__device__ float g_tw[T_TOK * 2];

__device__ __half g_xh[(size_t)T_TOK * H_DIM];
__device__ __half g_act[(size_t)TOTROW * F_DIM];
__device__ float  g_outp[(size_t)TOTROW * H_DIM];

// ---------------- helpers ----------------
__device__ __forceinline__ unsigned s2u(const void* p) {
    unsigned a;
    asm("{ .reg .u64 t; cvta.to.shared.u64 t, %1; cvt.u32.u64 %0, t; }" : "=r"(a) : "l"(p));
    return a;
}
// 128B-row swizzle: 16B chunk index XOR (row & 7)
__device__ __forceinline__ unsigned swz(int row, int chunk) {
    return (unsigned)(row * 128 + ((chunk ^ (row & 7)) << 4));
}
// load 8 fp32, convert to 8 fp16 packed in uint4
__device__ __forceinline__ uint4 ldcvt8(const float* p) {
    float4 u = *(const float4*)p;
    float4 v = *(const float4*)(p + 4);
    uint4 r;
    __half2 h0 = __floats2half2_rn(u.x, u.y);
    __half2 h1 = __floats2half2_rn(u.z, u.w);
    __half2 h2 = __floats2half2_rn(v.x, v.y);
    __half2 h3 = __floats2half2_rn(v.z, v.w);
    r.x = *(unsigned*)&h0; r.y = *(unsigned*)&h1;
    r.z = *(unsigned*)&h2; r.w = *(unsigned*)&h3;
    return r;
}

#define LDSM_X4(r0, r1, r2, r3, a)                                           \
    asm volatile("ldmatrix.sync.aligned.m8n8.x4.shared.b16 {%0,%1,%2,%3}, [%4];" \
                 : "=r"(r0), "=r"(r1), "=r"(r2), "=r"(r3) : "r"(a))

#define MMA16816(d, a, b0, b1)                                               \
    asm volatile("mma.sync.aligned.m16n8k16.row.col.f32.f16.f16.f32 "        \
                 "{%0,%1,%2,%3},{%4,%5,%6,%7},{%8,%9},{%0,%1,%2,%3};"        \
                 : "+f"((d)[0]), "+f"((d)[1]), "+f"((d)[2]), "+f"((d)[3])    \
                 : "r"((a)[0]), "r"((a)[1]), "r"((a)[2]), "r"((a)[3]),       \
                   "r"(b0), "r"(b1))

// ---------------- kernel: gating (also emits fp16 x) ----------------
__global__ void k_gate(const float* __restrict__ x, const float* __restrict__ gw) {
    __shared__ float sgw[H_DIM * N_EXP];
    for (int i = threadIdx.x; i < H_DIM * N_EXP; i += 256) sgw[i] = gw[i];
    __syncthreads();

    int warp = threadIdx.x >> 5, lane = threadIdx.x & 31;
    int t = blockIdx.x * 8 + warp;
    if (t >= T_TOK) return;

    float acc[N_EXP];
#pragma unroll
    for (int e = 0; e < N_EXP; e++) acc[e] = 0.f;
    const float* xr = x + (size_t)t * H_DIM;
    __half* xo = g_xh + (size_t)t * H_DIM;
    for (int h = lane; h < H_DIM; h += 32) {
        float xv = xr[h];
        xo[h] = __float2half_rn(xv);
#pragma unroll
        for (int e = 0; e < N_EXP; e++) acc[e] = fmaf(xv, sgw[h * N_EXP + e], acc[e]);
    }
#pragma unroll
    for (int e = 0; e < N_EXP; e++) {
#pragma unroll
        for (int o = 16; o > 0; o >>= 1) acc[e] += __shfl_xor_sync(0xffffffffu, acc[e], o);
    }
    if (lane == 0) {
        int e0 = 0; float m0 = acc[0];
#pragma unroll
        for (int e = 1; e < N_EXP; e++) if (acc[e] > m0) { m0 = acc[e]; e0 = e; }
        int e1 = -1; float m1 = -3.4e38f;
#pragma unroll
        for (int e = 0; e < N_EXP; e++) if (e != e0 && acc[e] > m1) { m1 = acc[e]; e1 = e; }
        float w0 = 1.f / (1.f + __expf(m1 - m0));
        g_te[2 * t] = e0;  g_te[2 * t + 1] = e1;
        g_tw[2 * t] = w0;  g_tw[2 * t + 1] = 1.f - w0;
    }
}

// ---------------- kernel: per-expert token lists ----------------
__global__ void k_build() {
    int e = threadIdx.x >> 5, lane = threadIdx.x & 31;
    int cnt = 0;
    for (int base = 0; base < T_TOK; base += 32) {
        int t = base + lane;
        int a = g_te[2 * t], b = g_te[2 * t + 1];
        bool f1 = (b == e);
        bool f  = (a == e) || f1;
        unsigned mask = __ballot_sync(0xffffffffu, f);
        int pos = cnt + __popc(mask & ((1u << lane) - 1u));
        if (f) {
            g_tok[e * CAP + pos] = t;
            g_tslot[2 * t + (f1 ? 1 : 0)] = pos;
        }
        cnt += __popc(mask);
    }
    if (lane == 0) g_count[e] = cnt;
    __syncthreads();
    if (threadIdx.x == 0) {
        int o = 0;
        for (int i = 0; i < N_EXP; i++) { g_off[i] = o; o += g_count[i]; }
    }
}

// ---------------- kernel: stage-1 (h = X w1^T, g = X w3^T) + SwiGLU ----------------
// R8 structure; weights read as fp32 and converted in the load path.
__global__ __launch_bounds__(256, 2) void k_ffn1(const float* __restrict__ w1,
                                                 const float* __restrict__ w3) {
    __shared__ __align__(1024) char sm[32768];

    int e = blockIdx.z;
    int count = g_count[e];
    int row0 = blockIdx.y * 128;
    if (row0 >= count) return;
    int fBase = blockIdx.x * 64;

    int tid = threadIdx.x, lane = tid & 31, wid = tid >> 5;
    int wm = wid >> 1, wn = wid & 1;
    unsigned sb = s2u(sm);
    const unsigned OA = 0, O1H = 16384, O3H = 24576;

    int jc = tid & 7;                 // 16B(half)/32B(float) chunk within row
    int rbase = tid >> 3;             // 0..31
    const __half* aptr[4];
#pragma unroll
    for (int it = 0; it < 4; it++) {
        int row = rbase + it * 32;
        int r = row0 + row;
        int tok = (r < count) ? g_tok[e * CAP + r] : -1;
        aptr[it] = (tok >= 0) ? (g_xh + (size_t)tok * H_DIM + jc * 8) : 0;
    }
    const float* w1p = w1 + ((size_t)e * F_DIM + fBase + rbase) * H_DIM + jc * 8;
    const float* w3p = w3 + ((size_t)e * F_DIM + fBase + rbase) * H_DIM + jc * 8;

    float acc1[2][4][4], acc3[2][4][4];
#pragma unroll
    for (int i = 0; i < 2; i++)
#pragma unroll
        for (int j = 0; j < 4; j++)
#pragma unroll
            for (int q = 0; q < 4; q++) { acc1[i][j][q] = 0.f; acc3[i][j][q] = 0.f; }

    for (int kt = 0; kt < H_DIM; kt += 64) {
#pragma unroll
        for (int it = 0; it < 4; it++) {
            int row = rbase + it * 32;
            uint4 v = make_uint4(0, 0, 0, 0);
            if (aptr[it]) v = *(const uint4*)(aptr[it] + kt);
            *(uint4*)(sm + OA + swz(row, jc)) = v;
        }
#pragma unroll
        for (int it = 0; it < 2; it++) {
            int row = rbase + it * 32;
            size_t go = (size_t)it * 32 * H_DIM + kt;
            unsigned d = swz(row, jc);
            *(uint4*)(sm + O1H + d) = ldcvt8(w1p + go);
            *(uint4*)(sm + O3H + d) = ldcvt8(w3p + go);
        }
        __syncthreads();

#pragma unroll
        for (int ks = 0; ks < 4; ks++) {
            unsigned af[2][4];
#pragma unroll
            for (int mt = 0; mt < 2; mt++) {
                int row = wm * 32 + mt * 16 + ((lane >> 3) & 1) * 8 + (lane & 7);
                int ch  = 2 * ks + (lane >> 4);
                LDSM_X4(af[mt][0], af[mt][1], af[mt][2], af[mt][3], sb + OA + swz(row, ch));
            }
            int wrow = wn * 32 + ((lane >> 4) & 1) * 8 + (lane & 7);
            int wch  = 2 * ks + ((lane >> 3) & 1);
#pragma unroll
            for (int ntp = 0; ntp < 4; ntp += 2) {
                unsigned d = swz(wrow + ntp * 8, wch);
                unsigned b1[4], b3[4];
                LDSM_X4(b1[0], b1[1], b1[2], b1[3], sb + O1H + d);
                LDSM_X4(b3[0], b3[1], b3[2], b3[3], sb + O3H + d);
#pragma unroll
                for (int mt = 0; mt < 2; mt++) {
                    MMA16816(acc1[mt][ntp],     af[mt], b1[0], b1[1]);
                    MMA16816(acc1[mt][ntp + 1], af[mt], b1[2], b1[3]);
                    MMA16816(acc3[mt][ntp],     af[mt], b3[0], b3[1]);
                    MMA16816(acc3[mt][ntp + 1], af[mt], b3[2], b3[3]);
                }
            }
        }
        __syncthreads();
    }

    // epilogue: SwiGLU -> fp16 activations
    int rb = row0 + wm * 32, cb = fBase + wn * 32;
    size_t obase = (size_t)g_off[e] * F_DIM;
#pragma unroll
    for (int mt = 0; mt < 2; mt++) {
#pragma unroll
        for (int nt = 0; nt < 4; nt++) {
            int r = rb + mt * 16 + (lane >> 2);
            int c = cb + nt * 8 + (lane & 3) * 2;
#pragma unroll
            for (int half = 0; half < 2; half++) {
                int rr = r + half * 8;
                if (rr < count) {
                    float h0 = acc1[mt][nt][half * 2],     g0 = acc3[mt][nt][half * 2];
                    float h1 = acc1[mt][nt][half * 2 + 1], g1 = acc3[mt][nt][half * 2 + 1];
                    float a0 = (h0 / (1.f + __expf(-h0))) * g0;
                    float a1 = (h1 / (1.f + __expf(-h1))) * g1;
                    __half2 v = __floats2half2_rn(a0, a1);
                    *(__half2*)(g_act + obase + (size_t)rr * F_DIM + c) = v;
                }
            }
        }
    }
}

// ---------------- kernel: stage-2 (out = act @ w2^T) ----------------
// R8 structure; w2 read as fp32 and converted in the load path.
__global__ __launch_bounds__(256, 2) void k_ffn2(const float* __restrict__ w2) {
    __shared__ __align__(1024) char sm[32768];

    int e = blockIdx.z;
    int count = g_count[e];
    int row0 = blockIdx.y * 128;
    if (row0 >= count) return;
    int hBase = blockIdx.x * 128;

    int tid = threadIdx.x, lane = tid & 31, wid = tid >> 5;
    int wm = wid >> 1, wn = wid & 1;
    unsigned sb = s2u(sm);
    const unsigned OA = 0, OBH = 16384;

    int rmax = count - row0; if (rmax > 128) rmax = 128;
    size_t rowBase = (size_t)(g_off[e] + row0);
    int jc = tid & 7, rbase = tid >> 3;

    const __half* apt[4];
    const float*  bpt[4];
#pragma unroll
    for (int it = 0; it < 4; it++) {
        int row = rbase + it * 32;
        apt[it] = (row < rmax) ? (g_act + (rowBase + row) * F_DIM + jc * 8) : 0;
        bpt[it] = w2 + ((size_t)e * H_DIM + hBase + row) * F_DIM + jc * 8;
    }

    float acc[2][8][4];
#pragma unroll
    for (int i = 0; i < 2; i++)
#pragma unroll
        for (int j = 0; j < 8; j++)
#pragma unroll
            for (int q = 0; q < 4; q++) acc[i][j][q] = 0.f;

    for (int kt = 0; kt < F_DIM; kt += 64) {
#pragma unroll
        for (int it = 0; it < 4; it++) {
            int row = rbase + it * 32;
            uint4 v = make_uint4(0, 0, 0, 0);
            if (apt[it]) v = *(const uint4*)(apt[it] + kt);
            *(uint4*)(sm + OA  + swz(row, jc)) = v;
            *(uint4*)(sm + OBH + swz(row, jc)) = ldcvt8(bpt[it] + kt);
        }
        __syncthreads();

#pragma unroll
        for (int ks = 0; ks < 4; ks++) {
            unsigned af[2][4];
#pragma unroll
            for (int mt = 0; mt < 2; mt++) {
                int row = wm * 32 + mt * 16 + ((lane >> 3) & 1) * 8 + (lane & 7);
                int ch  = 2 * ks + (lane >> 4);
                LDSM_X4(af[mt][0], af[mt][1], af[mt][2], af[mt][3], sb + OA + swz(row, ch));
            }
            int wrow = wn * 64 + ((lane >> 4) & 1) * 8 + (lane & 7);
            int wch  = 2 * ks + ((lane >> 3) & 1);
#pragma unroll
            for (int ntp = 0; ntp < 8; ntp += 2) {
                unsigned d = swz(wrow + ntp * 8, wch);
                unsigned bh[4];
                LDSM_X4(bh[0], bh[1], bh[2], bh[3], sb + OBH + d);
#pragma unroll
                for (int mt = 0; mt < 2; mt++) {
                    MMA16816(acc[mt][ntp],     af[mt], bh[0], bh[1]);
                    MMA16816(acc[mt][ntp + 1], af[mt], bh[2], bh[3]);
                }
            }
        }
        __syncthreads();
    }

    int rb = wm * 32, cb = hBase + wn * 64;
#pragma unroll
    for (int mt = 0; mt < 2; mt++) {
#pragma unroll
        for (int nt = 0; nt < 8; nt++) {
            int r = rb + mt * 16 + (lane >> 2);
            int c = cb + nt * 8 + (lane & 3) * 2;
#pragma unroll
            for (int half = 0; half < 2; half++) {
                int rr = r + half * 8;
                if (rr < rmax) {
                    float2 v = make_float2(acc[mt][nt][half * 2], acc[mt][nt][half * 2 + 1]);
                    *(float2*)(g_outp + (rowBase + rr) * H_DIM + c) = v;
                }
            }
        }
    }
}

// ---------------- kernel: weighted combine ----------------
__global__ void k_comb(float* __restrict__ out) {
    int t = blockIdx.x;
    int e0 = g_te[2 * t], e1 = g_te[2 * t + 1];
    int s0 = g_off[e0] + g_tslot[2 * t], s1 = g_off[e1] + g_tslot[2 * t + 1];
    float w0 = g_tw[2 * t], w1 = g_tw[2 * t + 1];
    const float4* p0 = (const float4*)(g_outp + (size_t)s0 * H_DIM);
    const float4* p1 = (const float4*)(g_outp + (size_t)s1 * H_DIM);
    float4* o = (float4*)(out + (size_t)t * H_DIM);
    for (int h = threadIdx.x; h < H_DIM / 4; h += 256) {
        float4 a = p0[h], b = p1[h];
        o[h] = make_float4(w0 * a.x + w1 * b.x, w0 * a.y + w1 * b.y,
                           w0 * a.z + w1 * b.z, w0 * a.w + w1 * b.w);
    }
}

// ---------------- launch (kernel launches ONLY, no dynamic smem) ----------------
extern "C" void kernel_launch(void* const* d_in, const int* in_sizes, int n_in,
                              void* d_out, int out_size) {
    const float* x  = (const float*)d_in[0];
    const float* gw = (const float*)d_in[1];
    const float* w1 = (const float*)d_in[2];
    const float* w3 = (const float*)d_in[3];
    const float* w2 = (const float*)d_in[4];
    float* out = (float*)d_out;

    k_gate<<<T_TOK / 8, 256>>>(x, gw);
    k_build<<<1, 256>>>();
    k_ffn1<<<dim3(F_DIM / 64, CAP / 128, N_EXP), 256>>>(w1, w3);
    k_ffn2<<<dim3(H_DIM / 128, CAP / 128, N_EXP), 256>>>(w2);
    k_comb<<<T_TOK, 256>>>(out);
}

// round 11
// speedup vs baseline: 1.3117x; 1.1784x over previous
#include <cuda_runtime.h>
#include <cuda_fp16.h>

#define T_TOK 2048
#define H_DIM 1024
#define F_DIM 3584
#define N_EXP 8
#define CAP   2048
#define TOTROW 4096

// ---------------- device scratch ----------------
__device__ int   g_count[N_EXP];
__device__ int   g_off[N_EXP];
__device__ int   g_tok[N_EXP * CAP];
__device__ int   g_te[T_TOK * 2];
__device__ int   g_tslot[T_TOK * 2];
__device__ float g_tw[T_TOK * 2];

__device__ __half g_xh[(size_t)T_TOK * H_DIM];
__device__ __half g_w1h[(size_t)N_EXP * F_DIM * H_DIM];
__device__ __half g_w3h[(size_t)N_EXP * F_DIM * H_DIM];
__device__ __half g_w2h[(size_t)N_EXP * H_DIM * F_DIM];
__device__ __half g_act[(size_t)TOTROW * F_DIM];
__device__ float  g_outp[(size_t)TOTROW * H_DIM];

// ---------------- helpers ----------------
__device__ __forceinline__ unsigned s2u(const void* p) {
    unsigned a;
    asm("{ .reg .u64 t; cvta.to.shared.u64 t, %1; cvt.u32.u64 %0, t; }" : "=r"(a) : "l"(p));
    return a;
}
// 128B-row swizzle: 16B chunk index XOR (row & 7)
__device__ __forceinline__ unsigned swz(int row, int chunk) {
    return (unsigned)(row * 128 + ((chunk ^ (row & 7)) << 4));
}

#define LDSM_X4(r0, r1, r2, r3, a)                                           \
    asm volatile("ldmatrix.sync.aligned.m8n8.x4.shared.b16 {%0,%1,%2,%3}, [%4];" \
                 : "=r"(r0), "=r"(r1), "=r"(r2), "=r"(r3) : "r"(a))

#define MMA16816(d, a, b0, b1)                                               \
    asm volatile("mma.sync.aligned.m16n8k16.row.col.f32.f16.f16.f32 "        \
                 "{%0,%1,%2,%3},{%4,%5,%6,%7},{%8,%9},{%0,%1,%2,%3};"        \
                 : "+f"((d)[0]), "+f"((d)[1]), "+f"((d)[2]), "+f"((d)[3])    \
                 : "r"((a)[0]), "r"((a)[1]), "r"((a)[2]), "r"((a)[3]),       \
                   "r"(b0), "r"(b1))

#define CP16(dst, src)                                                       \
    asm volatile("cp.async.cg.shared.global [%0], [%1], 16;"                 \
                 :: "r"(dst), "l"(src))
#define CP16Z(dst, src, ok)                                                  \
    asm volatile("cp.async.cg.shared.global [%0], [%1], 16, %2;"             \
                 :: "r"(dst), "l"(src), "r"((ok) ? 16 : 0))
#define CPCOMMIT() asm volatile("cp.async.commit_group;")
#define CPWAIT1()  asm volatile("cp.async.wait_group 1;")
#define CPWAIT0()  asm volatile("cp.async.wait_group 0;")

// ---------------- kernel: fused fp32 -> fp16 convert for w1, w3, w2 ----------------
__global__ void k_cvtw(const float* __restrict__ w1, const float* __restrict__ w3,
                       const float* __restrict__ w2) {
    const size_t nw4 = (size_t)N_EXP * F_DIM * H_DIM / 4;
    size_t i = (size_t)blockIdx.x * blockDim.x + threadIdx.x;
    size_t stride = (size_t)gridDim.x * blockDim.x;
    for (; i < 3 * nw4; i += stride) {
        const float* s; __half* d; size_t j = i;
        if (j < nw4)            { s = w1; d = g_w1h; }
        else if (j < 2 * nw4)   { s = w3; d = g_w3h; j -= nw4; }
        else                    { s = w2; d = g_w2h; j -= 2 * nw4; }
        float4 v = ((const float4*)s)[j];
        __half2 h0 = __floats2half2_rn(v.x, v.y);
        __half2 h1 = __floats2half2_rn(v.z, v.w);
        uint2 hv;
        hv.x = *(unsigned*)&h0; hv.y = *(unsigned*)&h1;
        ((uint2*)d)[j] = hv;
    }
}

// ---------------- kernel: gating (also emits fp16 x) ----------------
__global__ void k_gate(const float* __restrict__ x, const float* __restrict__ gw) {
    __shared__ float sgw[H_DIM * N_EXP];
    for (int i = threadIdx.x; i < H_DIM * N_EXP; i += 256) sgw[i] = gw[i];
    __syncthreads();

    int warp = threadIdx.x >> 5, lane = threadIdx.x & 31;
    int t = blockIdx.x * 8 + warp;
    if (t >= T_TOK) return;

    float acc[N_EXP];
#pragma unroll
    for (int e = 0; e < N_EXP; e++) acc[e] = 0.f;
    const float* xr = x + (size_t)t * H_DIM;
    __half* xo = g_xh + (size_t)t * H_DIM;
    for (int h = lane; h < H_DIM; h += 32) {
        float xv = xr[h];
        xo[h] = __float2half_rn(xv);
#pragma unroll
        for (int e = 0; e < N_EXP; e++) acc[e] = fmaf(xv, sgw[h * N_EXP + e], acc[e]);
    }
#pragma unroll
    for (int e = 0; e < N_EXP; e++) {
#pragma unroll
        for (int o = 16; o > 0; o >>= 1) acc[e] += __shfl_xor_sync(0xffffffffu, acc[e], o);
    }
    if (lane == 0) {
        int e0 = 0; float m0 = acc[0];
#pragma unroll
        for (int e = 1; e < N_EXP; e++) if (acc[e] > m0) { m0 = acc[e]; e0 = e; }
        int e1 = -1; float m1 = -3.4e38f;
#pragma unroll
        for (int e = 0; e < N_EXP; e++) if (e != e0 && acc[e] > m1) { m1 = acc[e]; e1 = e; }
        float w0 = 1.f / (1.f + __expf(m1 - m0));
        g_te[2 * t] = e0;  g_te[2 * t + 1] = e1;
        g_tw[2 * t] = w0;  g_tw[2 * t + 1] = 1.f - w0;
    }
}

// ---------------- kernel: per-expert token lists ----------------
__global__ void k_build() {
    int e = threadIdx.x >> 5, lane = threadIdx.x & 31;
    int cnt = 0;
    for (int base = 0; base < T_TOK; base += 32) {
        int t = base + lane;
        int a = g_te[2 * t], b = g_te[2 * t + 1];
        bool f1 = (b == e);
        bool f  = (a == e) || f1;
        unsigned mask = __ballot_sync(0xffffffffu, f);
        int pos = cnt + __popc(mask & ((1u << lane) - 1u));
        if (f) {
            g_tok[e * CAP + pos] = t;
            g_tslot[2 * t + (f1 ? 1 : 0)] = pos;
        }
        cnt += __popc(mask);
    }
    if (lane == 0) g_count[e] = cnt;
    __syncthreads();
    if (threadIdx.x == 0) {
        int o = 0;
        for (int i = 0; i < N_EXP; i++) { g_off[i] = o; o += g_count[i]; }
    }
}

// ---------------- kernel: stage-1 (h = X w1^T, g = X w3^T) + SwiGLU ----------------
// R10 MMA structure; 3-stage cp.async pipeline (stage = A 16K + W1 8K + W3 8K = 32KB).
__global__ __launch_bounds__(256, 2) void k_ffn1() {
    extern __shared__ char smraw[];
    unsigned sb = (s2u(smraw) + 1023u) & ~1023u;

    int e = blockIdx.z;
    int count = g_count[e];
    int row0 = blockIdx.y * 128;
    if (row0 >= count) return;
    int fBase = blockIdx.x * 64;

    int tid = threadIdx.x, lane = tid & 31, wid = tid >> 5;
    int wm = wid >> 1, wn = wid & 1;
    const unsigned STG = 32768, OA = 0, O1H = 16384, O3H = 24576;

    int jc = tid & 7;                 // 16B chunk within 128B row
    int rbase = tid >> 3;             // 0..31
    const __half* aptr[4];
#pragma unroll
    for (int it = 0; it < 4; it++) {
        int row = rbase + it * 32;
        int r = row0 + row;
        int tok = (r < count) ? g_tok[e * CAP + r] : -1;
        aptr[it] = (tok >= 0) ? (g_xh + (size_t)tok * H_DIM + jc * 8) : 0;
    }
    const __half* w1p0 = g_w1h + ((size_t)e * F_DIM + fBase + rbase) * H_DIM + jc * 8;
    const __half* w1p1 = w1p0 + (size_t)32 * H_DIM;
    const __half* w3p0 = g_w3h + ((size_t)e * F_DIM + fBase + rbase) * H_DIM + jc * 8;
    const __half* w3p1 = w3p0 + (size_t)32 * H_DIM;

#define F1_LOAD(kt, st) do {                                                 \
    unsigned b_ = sb + (st) * STG;                                           \
    _Pragma("unroll")                                                        \
    for (int it_ = 0; it_ < 4; it_++) {                                      \
        int row_ = rbase + it_ * 32;                                         \
        CP16Z(b_ + OA + swz(row_, jc),                                       \
              aptr[it_] ? (aptr[it_] + (kt)) : g_xh, aptr[it_] != 0);        \
    }                                                                        \
    CP16(b_ + O1H + swz(rbase,      jc), w1p0 + (kt));                       \
    CP16(b_ + O1H + swz(rbase + 32, jc), w1p1 + (kt));                       \
    CP16(b_ + O3H + swz(rbase,      jc), w3p0 + (kt));                       \
    CP16(b_ + O3H + swz(rbase + 32, jc), w3p1 + (kt));                       \
} while (0)

    float acc1[2][4][4], acc3[2][4][4];
#pragma unroll
    for (int i = 0; i < 2; i++)
#pragma unroll
        for (int j = 0; j < 4; j++)
#pragma unroll
            for (int q = 0; q < 4; q++) { acc1[i][j][q] = 0.f; acc3[i][j][q] = 0.f; }

    F1_LOAD(0, 0);  CPCOMMIT();
    F1_LOAD(64, 1); CPCOMMIT();

    const int NIT = H_DIM / 64;   // 16
    for (int it = 0; it < NIT; it++) {
        int s = it % 3;
        if (it + 1 < NIT) CPWAIT1(); else CPWAIT0();
        __syncthreads();
        if (it + 2 < NIT) { F1_LOAD((it + 2) * 64, (it + 2) % 3); CPCOMMIT(); }

        unsigned base = sb + s * STG;
#pragma unroll
        for (int ks = 0; ks < 4; ks++) {
            unsigned af[2][4];
#pragma unroll
            for (int mt = 0; mt < 2; mt++) {
                int row = wm * 32 + mt * 16 + ((lane >> 3) & 1) * 8 + (lane & 7);
                int ch  = 2 * ks + (lane >> 4);
                LDSM_X4(af[mt][0], af[mt][1], af[mt][2], af[mt][3], base + OA + swz(row, ch));
            }
            int wrow = wn * 32 + ((lane >> 4) & 1) * 8 + (lane & 7);
            int wch  = 2 * ks + ((lane >> 3) & 1);
#pragma unroll
            for (int ntp = 0; ntp < 4; ntp += 2) {
                unsigned d = swz(wrow + ntp * 8, wch);
                unsigned b1[4], b3[4];
                LDSM_X4(b1[0], b1[1], b1[2], b1[3], base + O1H + d);
                LDSM_X4(b3[0], b3[1], b3[2], b3[3], base + O3H + d);
#pragma unroll
                for (int mt = 0; mt < 2; mt++) {
                    MMA16816(acc1[mt][ntp],     af[mt], b1[0], b1[1]);
                    MMA16816(acc1[mt][ntp + 1], af[mt], b1[2], b1[3]);
                    MMA16816(acc3[mt][ntp],     af[mt], b3[0], b3[1]);
                    MMA16816(acc3[mt][ntp + 1], af[mt], b3[2], b3[3]);
                }
            }
        }
    }

    // epilogue: SwiGLU -> fp16 activations
    int rb = row0 + wm * 32, cb = fBase + wn * 32;
    size_t obase = (size_t)g_off[e] * F_DIM;
#pragma unroll
    for (int mt = 0; mt < 2; mt++) {
#pragma unroll
        for (int nt = 0; nt < 4; nt++) {
            int r = rb + mt * 16 + (lane >> 2);
            int c = cb + nt * 8 + (lane & 3) * 2;
#pragma unroll
            for (int half = 0; half < 2; half++) {
                int rr = r + half * 8;
                if (rr < count) {
                    float h0 = acc1[mt][nt][half * 2],     g0 = acc3[mt][nt][half * 2];
                    float h1 = acc1[mt][nt][half * 2 + 1], g1 = acc3[mt][nt][half * 2 + 1];
                    float a0 = (h0 / (1.f + __expf(-h0))) * g0;
                    float a1 = (h1 / (1.f + __expf(-h1))) * g1;
                    __half2 v = __floats2half2_rn(a0, a1);
                    *(__half2*)(g_act + obase + (size_t)rr * F_DIM + c) = v;
                }
            }
        }
    }
}

// ---------------- kernel: stage-2 (out = act @ w2^T) ----------------
// R10 MMA structure; 3-stage cp.async pipeline (stage = A 16K + B 16K = 32KB).
__global__ __launch_bounds__(256, 2) void k_ffn2() {
    extern __shared__ char smraw[];
    unsigned sb = (s2u(smraw) + 1023u) & ~1023u;

    int e = blockIdx.z;
    int count = g_count[e];
    int row0 = blockIdx.y * 128;
    if (row0 >= count) return;
    int hBase = blockIdx.x * 128;

    int tid = threadIdx.x, lane = tid & 31, wid = tid >> 5;
    int wm = wid >> 1, wn = wid & 1;
    const unsigned STG = 32768, OA = 0, OBH = 16384;

    int rmax = count - row0; if (rmax > 128) rmax = 128;
    size_t rowBase = (size_t)(g_off[e] + row0);
    int jc = tid & 7, rbase = tid >> 3;

    const __half* apt[4];
    const __half* bpt[4];
#pragma unroll
    for (int it = 0; it < 4; it++) {
        int row = rbase + it * 32;
        apt[it] = (row < rmax) ? (g_act + (rowBase + row) * F_DIM + jc * 8) : 0;
        bpt[it] = g_w2h + ((size_t)e * H_DIM + hBase + row) * F_DIM + jc * 8;
    }

#define F2_LOAD(kt, st) do {                                                 \
    unsigned b_ = sb + (st) * STG;                                           \
    _Pragma("unroll")                                                        \
    for (int it_ = 0; it_ < 4; it_++) {                                      \
        int row_ = rbase + it_ * 32;                                         \
        CP16Z(b_ + OA + swz(row_, jc),                                       \
              apt[it_] ? (apt[it_] + (kt)) : g_act, apt[it_] != 0);          \
        CP16(b_ + OBH + swz(row_, jc), bpt[it_] + (kt));                     \
    }                                                                        \
} while (0)

    float acc[2][8][4];
#pragma unroll
    for (int i = 0; i < 2; i++)
#pragma unroll
        for (int j = 0; j < 8; j++)
#pragma unroll
            for (int q = 0; q < 4; q++) acc[i][j][q] = 0.f;

    F2_LOAD(0, 0);  CPCOMMIT();
    F2_LOAD(64, 1); CPCOMMIT();

    const int NIT = F_DIM / 64;   // 56
    for (int it = 0; it < NIT; it++) {
        int s = it % 3;
        if (it + 1 < NIT) CPWAIT1(); else CPWAIT0();
        __syncthreads();
        if (it + 2 < NIT) { F2_LOAD((it + 2) * 64, (it + 2) % 3); CPCOMMIT(); }

        unsigned base = sb + s * STG;
#pragma unroll
        for (int ks = 0; ks < 4; ks++) {
            unsigned af[2][4];
#pragma unroll
            for (int mt = 0; mt < 2; mt++) {
                int row = wm * 32 + mt * 16 + ((lane >> 3) & 1) * 8 + (lane & 7);
                int ch  = 2 * ks + (lane >> 4);
                LDSM_X4(af[mt][0], af[mt][1], af[mt][2], af[mt][3], base + OA + swz(row, ch));
            }
            int wrow = wn * 64 + ((lane >> 4) & 1) * 8 + (lane & 7);
            int wch  = 2 * ks + ((lane >> 3) & 1);
#pragma unroll
            for (int ntp = 0; ntp < 8; ntp += 2) {
                unsigned d = swz(wrow + ntp * 8, wch);
                unsigned bh[4];
                LDSM_X4(bh[0], bh[1], bh[2], bh[3], base + OBH + d);
#pragma unroll
                for (int mt = 0; mt < 2; mt++) {
                    MMA16816(acc[mt][ntp],     af[mt], bh[0], bh[1]);
                    MMA16816(acc[mt][ntp + 1], af[mt], bh[2], bh[3]);
                }
            }
        }
    }

    int rb = wm * 32, cb = hBase + wn * 64;
#pragma unroll
    for (int mt = 0; mt < 2; mt++) {
#pragma unroll
        for (int nt = 0; nt < 8; nt++) {
            int r = rb + mt * 16 + (lane >> 2);
            int c = cb + nt * 8 + (lane & 3) * 2;
#pragma unroll
            for (int half = 0; half < 2; half++) {
                int rr = r + half * 8;
                if (rr < rmax) {
                    float2 v = make_float2(acc[mt][nt][half * 2], acc[mt][nt][half * 2 + 1]);
                    *(float2*)(g_outp + (rowBase + rr) * H_DIM + c) = v;
                }
            }
        }
    }
}

// ---------------- kernel: weighted combine ----------------
__global__ void k_comb(float* __restrict__ out) {
    int t = blockIdx.x;
    int e0 = g_te[2 * t], e1 = g_te[2 * t + 1];
    int s0 = g_off[e0] + g_tslot[2 * t], s1 = g_off[e1] + g_tslot[2 * t + 1];
    float w0 = g_tw[2 * t], w1 = g_tw[2 * t + 1];
    const float4* p0 = (const float4*)(g_outp + (size_t)s0 * H_DIM);
    const float4* p1 = (const float4*)(g_outp + (size_t)s1 * H_DIM);
    float4* o = (float4*)(out + (size_t)t * H_DIM);
    for (int h = threadIdx.x; h < H_DIM / 4; h += 256) {
        float4 a = p0[h], b = p1[h];
        o[h] = make_float4(w0 * a.x + w1 * b.x, w0 * a.y + w1 * b.y,
                           w0 * a.z + w1 * b.z, w0 * a.w + w1 * b.w);
    }
}

// ---------------- launch ----------------
#define SMEM_PIPE (3 * 32768 + 1024)

extern "C" void kernel_launch(void* const* d_in, const int* in_sizes, int n_in,
                              void* d_out, int out_size) {
    const float* x  = (const float*)d_in[0];
    const float* gw = (const float*)d_in[1];
    const float* w1 = (const float*)d_in[2];
    const float* w3 = (const float*)d_in[3];
    const float* w2 = (const float*)d_in[4];
    float* out = (float*)d_out;

    // opt-in to >48KB dynamic smem (not a stream op; capture-safe)
    cudaFuncSetAttribute(k_ffn1, cudaFuncAttributeMaxDynamicSharedMemorySize, SMEM_PIPE);
    cudaFuncSetAttribute(k_ffn2, cudaFuncAttributeMaxDynamicSharedMemorySize, SMEM_PIPE);

    k_gate<<<T_TOK / 8, 256>>>(x, gw);
    k_build<<<1, 256>>>();
    k_cvtw<<<16384, 256>>>(w1, w3, w2);
    k_ffn1<<<dim3(F_DIM / 64, CAP / 128, N_EXP), 256, SMEM_PIPE>>>();
    k_ffn2<<<dim3(H_DIM / 128, CAP / 128, N_EXP), 256, SMEM_PIPE>>>();
    k_comb<<<T_TOK, 256>>>(out);
}